// round 7
// baseline (speedup 1.0000x reference)
#include <cuda_runtime.h>
#include <cuda_bf16.h>
#include <cstdint>

#define SEQ 1600
#define SP  1664          /* padded seq: 13 * 128 */
#define BH  64
#define NKT 13
#define OUT_ELEMS (8*SEQ*512)

// -------------------- scratch (device globals, zero-initialized) --------------------
__device__ __nv_bfloat16 g_qh[(size_t)BH*SP*64];
__device__ __nv_bfloat16 g_ql[(size_t)BH*SP*64];
__device__ __nv_bfloat16 g_kh[(size_t)BH*SP*64];
__device__ __nv_bfloat16 g_kl[(size_t)BH*SP*64];
__device__ __nv_bfloat16 g_vh[(size_t)BH*64*SEQ];   // [bh][d][s] transposed
__device__ __nv_bfloat16 g_vl[(size_t)BH*64*SEQ];
__device__ float g_partial[(size_t)BH*SEQ*NKT];
__device__ float g_rowinv[(size_t)BH*SEQ];

// -------------------- f32x2 helpers --------------------
typedef unsigned long long ull;
__device__ __forceinline__ ull pk2(float a, float b) {
    ull r; asm("mov.b64 %0, {%1, %2};" : "=l"(r) : "f"(a), "f"(b)); return r;
}
__device__ __forceinline__ float2 upk2(ull v) {
    float2 f; asm("mov.b64 {%0, %1}, %2;" : "=f"(f.x), "=f"(f.y) : "l"(v)); return f;
}
__device__ __forceinline__ ull fma2(ull a, ull b, ull c) {
    ull d; asm("fma.rn.f32x2 %0, %1, %2, %3;" : "=l"(d) : "l"(a), "l"(b), "l"(c)); return d;
}

#define MAINSTEP(As_row, Bs_row) do {                                   \
    const float4 a0 = *(const float4*)((As_row) + ty*8);                \
    const float4 a1 = *(const float4*)((As_row) + ty*8 + 4);            \
    const ulonglong2 b0 = *(const ulonglong2*)((Bs_row) + tx*8);        \
    const ulonglong2 b1 = *(const ulonglong2*)((Bs_row) + tx*8 + 4);    \
    const float av[8] = {a0.x,a0.y,a0.z,a0.w,a1.x,a1.y,a1.z,a1.w};      \
    _Pragma("unroll")                                                   \
    for (int _i = 0; _i < 8; _i++) {                                    \
        const ull aa = pk2(av[_i], av[_i]);                             \
        acc[_i][0] = fma2(aa, b0.x, acc[_i][0]);                        \
        acc[_i][1] = fma2(aa, b0.y, acc[_i][1]);                        \
        acc[_i][2] = fma2(aa, b1.x, acc[_i][2]);                        \
        acc[_i][3] = fma2(aa, b1.y, acc[_i][3]);                        \
    } } while (0)

// -------------------- mma.sync / ldmatrix helpers --------------------
__device__ __forceinline__ uint32_t smem_u32(const void* p_) {
    uint32_t a;
    asm("{ .reg .u64 t; cvta.to.shared.u64 t, %1; cvt.u32.u64 %0, t; }" : "=r"(a) : "l"(p_));
    return a;
}
__device__ __forceinline__ void ldsm4(uint32_t* r, uint32_t addr) {
    asm volatile("ldmatrix.sync.aligned.m8n8.x4.shared.b16 {%0,%1,%2,%3}, [%4];"
                 : "=r"(r[0]), "=r"(r[1]), "=r"(r[2]), "=r"(r[3]) : "r"(addr));
}
__device__ __forceinline__ void mma16816(float* d, const uint32_t* a, const uint32_t* b) {
    asm volatile("mma.sync.aligned.m16n8k16.row.col.f32.bf16.bf16.f32 "
                 "{%0,%1,%2,%3}, {%4,%5,%6,%7}, {%8,%9}, {%0,%1,%2,%3};"
                 : "+f"(d[0]), "+f"(d[1]), "+f"(d[2]), "+f"(d[3])
                 : "r"(a[0]), "r"(a[1]), "r"(a[2]), "r"(a[3]), "r"(b[0]), "r"(b[1]));
}

// ==================== K1: QKV projection (256 thr, 128x128 tiles) ====================
__global__ __launch_bounds__(256) void proj_kernel(
    const float* __restrict__ x,
    const float* __restrict__ wq, const float* __restrict__ bq,
    const float* __restrict__ wk, const float* __restrict__ bk,
    const float* __restrict__ wv, const float* __restrict__ bv)
{
    __shared__ __align__(16) float As[16*132];
    __shared__ __align__(16) float Bs[16*132];
    const int tid = threadIdx.x, tx = tid & 15, ty = tid >> 4;
    const int m0 = blockIdx.x*128, n0 = blockIdx.y*128, mat = blockIdx.z;
    const float* w  = (mat==0) ? wq : ((mat==1) ? wk : wv);
    const float* bb = (mat==0) ? bq : ((mat==1) ? bk : bv);

    ull acc[8][4];
    #pragma unroll
    for (int i = 0; i < 8; i++)
        #pragma unroll
        for (int j = 0; j < 4; j++) acc[i][j] = 0ULL;

    for (int kc = 0; kc < 256; kc += 16) {
        #pragma unroll
        for (int j = 0; j < 2; j++) {
            const int idx = tid + j*256;
            const int r = idx >> 2, c4 = idx & 3;
            float4 v = *(const float4*)&x[(size_t)(m0 + r)*256 + kc + c4*4];
            As[(c4*4+0)*132 + r] = v.x;
            As[(c4*4+1)*132 + r] = v.y;
            As[(c4*4+2)*132 + r] = v.z;
            As[(c4*4+3)*132 + r] = v.w;
        }
        #pragma unroll
        for (int j = 0; j < 2; j++) {
            const int idx = tid + j*256;
            const int r = idx >> 5, c = idx & 31;
            *(float4*)&Bs[r*132 + c*4] = *(const float4*)&w[(size_t)(kc + r)*512 + n0 + c*4];
        }
        __syncthreads();
        #pragma unroll
        for (int kk = 0; kk < 16; kk++) MAINSTEP(&As[kk*132], &Bs[kk*132]);
        __syncthreads();
    }

    const int n_base = n0 + tx*8;
    const int h = n_base >> 6, d0 = n_base & 63;
    float b8[8];
    #pragma unroll
    for (int j = 0; j < 8; j++) b8[j] = bb[n_base + j];

    const int m_base = m0 + ty*8;
    const int bI = m_base / SEQ, sI0 = m_base % SEQ;
    const int bh = bI*8 + h;

    if (mat == 2) {
        #pragma unroll
        for (int j = 0; j < 8; j++) {
            uint32_t hp[4], lp[4];
            #pragma unroll
            for (int i2 = 0; i2 < 4; i2++) {
                float v0, v1;
                {
                    float2 t = upk2(acc[i2*2][j>>1]);
                    v0 = ((j & 1) ? t.y : t.x) + b8[j];
                }
                {
                    float2 t = upk2(acc[i2*2+1][j>>1]);
                    v1 = ((j & 1) ? t.y : t.x) + b8[j];
                }
                v0 = fmaxf(v0, 0.f); v1 = fmaxf(v1, 0.f);
                __nv_bfloat16 h0 = __float2bfloat16(v0), h1 = __float2bfloat16(v1);
                __nv_bfloat16 l0 = __float2bfloat16(v0 - __bfloat162float(h0));
                __nv_bfloat16 l1 = __float2bfloat16(v1 - __bfloat162float(h1));
                hp[i2] = (uint32_t)__bfloat16_as_ushort(h0) | ((uint32_t)__bfloat16_as_ushort(h1) << 16);
                lp[i2] = (uint32_t)__bfloat16_as_ushort(l0) | ((uint32_t)__bfloat16_as_ushort(l1) << 16);
            }
            const size_t off = ((size_t)bh*64 + d0 + j)*SEQ + sI0;
            *(uint4*)&g_vh[off] = make_uint4(hp[0], hp[1], hp[2], hp[3]);
            *(uint4*)&g_vl[off] = make_uint4(lp[0], lp[1], lp[2], lp[3]);
        }
    } else {
        const float sc = (mat == 0) ? 0.125f : 1.0f;
        __nv_bfloat16* dh = (mat == 0) ? g_qh : g_kh;
        __nv_bfloat16* dl = (mat == 0) ? g_ql : g_kl;
        #pragma unroll
        for (int i = 0; i < 8; i++) {
            float o[8];
            #pragma unroll
            for (int j = 0; j < 4; j++) {
                float2 t = upk2(acc[i][j]);
                o[j*2] = (t.x + b8[j*2]) * sc; o[j*2+1] = (t.y + b8[j*2+1]) * sc;
            }
            uint32_t hw[4], lw[4];
            #pragma unroll
            for (int j = 0; j < 4; j++) {
                __nv_bfloat16 h0 = __float2bfloat16(o[j*2]);
                __nv_bfloat16 h1 = __float2bfloat16(o[j*2+1]);
                __nv_bfloat16 l0 = __float2bfloat16(o[j*2]   - __bfloat162float(h0));
                __nv_bfloat16 l1 = __float2bfloat16(o[j*2+1] - __bfloat162float(h1));
                hw[j] = (uint32_t)__bfloat16_as_ushort(h0) | ((uint32_t)__bfloat16_as_ushort(h1) << 16);
                lw[j] = (uint32_t)__bfloat16_as_ushort(l0) | ((uint32_t)__bfloat16_as_ushort(l1) << 16);
            }
            const size_t off = ((size_t)bh*SP + sI0 + i)*64 + d0;
            *(uint4*)&dh[off] = make_uint4(hw[0], hw[1], hw[2], hw[3]);
            *(uint4*)&dl[off] = make_uint4(lw[0], lw[1], lw[2], lw[3]);
        }
    }
}

// ==================== K2: mma.sync score tile (64q x 128k) ====================
#define SC_SMEM_BYTES (27648*2)

__global__ __launch_bounds__(128) void score_kernel(float* __restrict__ p)
{
    extern __shared__ __align__(16) __nv_bfloat16 sm[];
    __nv_bfloat16* QH = sm;
    __nv_bfloat16* QL = sm + 4608;
    __nv_bfloat16* KH = sm + 9216;
    __nv_bfloat16* KL = sm + 18432;
    __shared__ float sums[4][64];

    const int tid = threadIdx.x, w = tid >> 5, lane = tid & 31;
    const int kt = blockIdx.x, qt = blockIdx.y, bh = blockIdx.z;
    const int q0 = qt*64, k0 = kt*128;

    {
        const uint4* sqh = (const uint4*)(g_qh + ((size_t)bh*SP + q0)*64);
        const uint4* sql = (const uint4*)(g_ql + ((size_t)bh*SP + q0)*64);
        #pragma unroll
        for (int it = 0; it < 4; it++) {
            const int i = tid + it*128;
            const int r = i >> 3, c = i & 7;
            *(uint4*)&QH[r*72 + c*8] = sqh[i];
            *(uint4*)&QL[r*72 + c*8] = sql[i];
        }
        const uint4* skh = (const uint4*)(g_kh + ((size_t)bh*SP + k0)*64);
        const uint4* skl = (const uint4*)(g_kl + ((size_t)bh*SP + k0)*64);
        #pragma unroll
        for (int it = 0; it < 8; it++) {
            const int i = tid + it*128;
            const int r = i >> 3, c = i & 7;
            *(uint4*)&KH[r*72 + c*8] = skh[i];
            *(uint4*)&KL[r*72 + c*8] = skl[i];
        }
    }
    __syncthreads();

    float acc[4][4][4];
    #pragma unroll
    for (int a = 0; a < 4; a++)
        #pragma unroll
        for (int b = 0; b < 4; b++)
            #pragma unroll
            for (int c = 0; c < 4; c++) acc[a][b][c] = 0.f;

    const uint32_t aQH = smem_u32(QH), aQL = smem_u32(QL);
    const uint32_t aKH = smem_u32(KH), aKL = smem_u32(KL);

    const int arow = lane & 15, akoff8 = (lane >> 4) * 8;
    const int mi = lane >> 3, l8 = lane & 7;
    const int brow = (mi >> 1)*8 + l8, bkoff8 = (mi & 1)*8;

    #pragma unroll
    for (int kc = 0; kc < 4; kc++) {
        uint32_t ah[4][4], al[4][4], bhf[2][4], blf[2][4];
        const int ak = kc*16 + akoff8;
        #pragma unroll
        for (int mb = 0; mb < 4; mb++) {
            const uint32_t off = (uint32_t)(((mb*16 + arow)*72 + ak) * 2);
            ldsm4(ah[mb], aQH + off);
            ldsm4(al[mb], aQL + off);
        }
        const int bk = kc*16 + bkoff8;
        #pragma unroll
        for (int nbp = 0; nbp < 2; nbp++) {
            const int n = w*32 + nbp*16 + brow;
            const uint32_t off = (uint32_t)((n*72 + bk) * 2);
            ldsm4(bhf[nbp], aKH + off);
            ldsm4(blf[nbp], aKL + off);
        }
        #pragma unroll
        for (int mb = 0; mb < 4; mb++)
            #pragma unroll
            for (int nb = 0; nb < 4; nb++) {
                const int nbp = nb >> 1, sel = (nb & 1)*2;
                mma16816(acc[mb][nb], ah[mb], &bhf[nbp][sel]);
                mma16816(acc[mb][nb], ah[mb], &blf[nbp][sel]);
                mma16816(acc[mb][nb], al[mb], &bhf[nbp][sel]);
            }
    }

    const int r0 = lane >> 2;
    const int c0 = (lane & 3) * 2;
    #pragma unroll
    for (int mb = 0; mb < 4; mb++) {
        const int q1 = q0 + mb*16 + r0, q2 = q1 + 8;
        const int qf1 = q1 / 25, qf2 = q2 / 25;
        float s1 = 0.f, s2 = 0.f;
        #pragma unroll
        for (int nb = 0; nb < 4; nb++) {
            const int k = k0 + w*32 + nb*8 + c0;
            const int kfa = k / 25, kfb = (k + 1) / 25;
            const bool kv = (k < SEQ);
            float e0 = (kv && (qf1 != kfa || q1 == k  )) ? __expf(acc[mb][nb][0]) : 0.f;
            float e1 = (kv && (qf1 != kfb || q1 == k+1)) ? __expf(acc[mb][nb][1]) : 0.f;
            float e2 = (kv && (qf2 != kfa || q2 == k  )) ? __expf(acc[mb][nb][2]) : 0.f;
            float e3 = (kv && (qf2 != kfb || q2 == k+1)) ? __expf(acc[mb][nb][3]) : 0.f;
            s1 += e0 + e1; s2 += e2 + e3;
            if (kv) {
                if (q1 < SEQ) *(float2*)&p[((size_t)bh*SEQ + q1)*SEQ + k] = make_float2(e0, e1);
                if (q2 < SEQ) *(float2*)&p[((size_t)bh*SEQ + q2)*SEQ + k] = make_float2(e2, e3);
            }
        }
        s1 += __shfl_xor_sync(0xffffffffu, s1, 1);
        s1 += __shfl_xor_sync(0xffffffffu, s1, 2);
        s2 += __shfl_xor_sync(0xffffffffu, s2, 1);
        s2 += __shfl_xor_sync(0xffffffffu, s2, 2);
        if ((lane & 3) == 0) {
            sums[w][mb*16 + r0]     = s1;
            sums[w][mb*16 + 8 + r0] = s2;
        }
    }
    __syncthreads();
    if (tid < 64) {
        const int q = q0 + tid;
        if (q < SEQ)
            g_partial[((size_t)bh*SEQ + q)*NKT + kt] =
                (sums[0][tid] + sums[1][tid]) + (sums[2][tid] + sums[3][tid]);
    }
}

// ==================== K3: row inverse ====================
__global__ __launch_bounds__(256) void rowinv_kernel()
{
    const int row = blockIdx.x*256 + threadIdx.x;
    if (row >= BH*SEQ) return;
    float s = 0.f;
    #pragma unroll
    for (int t = 0; t < NKT; t++) s += g_partial[(size_t)row*NKT + t];
    g_rowinv[row] = 1.0f / s;
}

// ==================== K4: pipelined tensor-core PV ====================
// dyn smem (bytes): AH[2][128*72] AL[2][128*72] VH[2][64*72] VL[2][64*72]
#define PV_A_BUF   18432                     /* 128*72*2B */
#define PV_V_BUF    9216                     /* 64*72*2B  */
#define PV_OFF_AL  (2*PV_A_BUF)
#define PV_OFF_VH  (4*PV_A_BUF)
#define PV_OFF_VL  (4*PV_A_BUF + 2*PV_V_BUF)
#define PV_SMEM_BYTES (4*PV_A_BUF + 4*PV_V_BUF)   /* 110592 */

__global__ __launch_bounds__(256, 2) void pv_kernel(float* __restrict__ p, float* __restrict__ out)
{
    extern __shared__ __align__(16) char smc[];
    __shared__ float rs[128];

    const int tid = threadIdx.x, w = tid >> 5, lane = tid & 31;
    const int qt = blockIdx.x, bh = blockIdx.y;
    const int q0 = qt*128;

    if (tid < 128) {
        const int q = q0 + tid;
        rs[tid] = (q < SEQ) ? g_rowinv[(size_t)bh*SEQ + q] : 0.f;
    }
    __syncthreads();

    // e-load mapping: 2 threads per row, 32 floats each
    const int er = tid >> 1, eh = (tid & 1) * 32;
    const int q_er = q0 + er;
    const bool ev = (q_er < SEQ);
    float* prow = p + ((size_t)bh*SEQ + (ev ? q_er : 0))*SEQ + eh;
    // V-load mapping: 2 uint4 per thread
    int vr[2], vc[2];
    #pragma unroll
    for (int j = 0; j < 2; j++) { const int i = tid + j*256; vr[j] = i >> 3; vc[j] = (i & 7)*8; }

    const uint32_t sbase = smem_u32(smc);

    float4 ebuf[8];
    uint4 vbh[2], vbl[2];

    float acc[8][4];
    #pragma unroll
    for (int i = 0; i < 8; i++)
        #pragma unroll
        for (int j = 0; j < 4; j++) acc[i][j] = 0.f;

    const int arow = lane & 15, ak8 = (lane >> 4)*8;
    const int mi = lane >> 3, l8 = lane & 7;

    // ---- lambda-free helpers via macros ----
#define PV_LOAD(c) do {                                                       \
        const int s0_ = (c)*64;                                               \
        _Pragma("unroll")                                                     \
        for (int j = 0; j < 8; j++)                                           \
            ebuf[j] = ev ? *(const float4*)(prow + s0_ + j*4)                 \
                         : make_float4(0.f,0.f,0.f,0.f);                      \
        _Pragma("unroll")                                                     \
        for (int j = 0; j < 2; j++) {                                         \
            const size_t src_ = ((size_t)bh*64 + vr[j])*SEQ + s0_ + vc[j];    \
            vbh[j] = *(const uint4*)&g_vh[src_];                              \
            vbl[j] = *(const uint4*)&g_vl[src_];                              \
        } } while (0)

#define PV_PROCESS(c, bf) do {                                                \
        const int s0_ = (c)*64;                                               \
        const float rv_ = rs[er];                                             \
        char* AHb_ = smc + (bf)*PV_A_BUF;                                     \
        char* ALb_ = smc + PV_OFF_AL + (bf)*PV_A_BUF;                         \
        _Pragma("unroll")                                                     \
        for (int j = 0; j < 8; j++) {                                         \
            float4 e4 = ebuf[j];                                              \
            e4.x *= rv_; e4.y *= rv_; e4.z *= rv_; e4.w *= rv_;               \
            if (ev) *(float4*)(prow + s0_ + j*4) = e4;                        \
            __nv_bfloat162 h01 = __float22bfloat162_rn(make_float2(e4.x, e4.y)); \
            __nv_bfloat162 h23 = __float22bfloat162_rn(make_float2(e4.z, e4.w)); \
            float2 hf01 = __bfloat1622float2(h01), hf23 = __bfloat1622float2(h23); \
            __nv_bfloat162 l01 = __float22bfloat162_rn(make_float2(e4.x-hf01.x, e4.y-hf01.y)); \
            __nv_bfloat162 l23 = __float22bfloat162_rn(make_float2(e4.z-hf23.x, e4.w-hf23.y)); \
            *(uint2*)(AHb_ + (er*72 + eh + j*4)*2) =                          \
                make_uint2(*(uint32_t*)&h01, *(uint32_t*)&h23);               \
            *(uint2*)(ALb_ + (er*72 + eh + j*4)*2) =                          \
                make_uint2(*(uint32_t*)&l01, *(uint32_t*)&l23);               \
        }                                                                     \
        char* VHb_ = smc + PV_OFF_VH + (bf)*PV_V_BUF;                         \
        char* VLb_ = smc + PV_OFF_VL + (bf)*PV_V_BUF;                         \
        _Pragma("unroll")                                                     \
        for (int j = 0; j < 2; j++) {                                         \
            *(uint4*)(VHb_ + (vr[j]*72 + vc[j])*2) = vbh[j];                  \
            *(uint4*)(VLb_ + (vr[j]*72 + vc[j])*2) = vbl[j];                  \
        } } while (0)

#define PV_MMA(bf) do {                                                       \
        const uint32_t aAH_ = sbase + (bf)*PV_A_BUF;                          \
        const uint32_t aAL_ = sbase + PV_OFF_AL + (bf)*PV_A_BUF;              \
        const uint32_t aVH_ = sbase + PV_OFF_VH + (bf)*PV_V_BUF;              \
        const uint32_t aVL_ = sbase + PV_OFF_VL + (bf)*PV_V_BUF;              \
        _Pragma("unroll")                                                     \
        for (int kc = 0; kc < 4; kc++) {                                      \
            uint32_t ah_[4], al_[4], bhf_[4][4], blf_[4][4];                  \
            const uint32_t aoff_ = (uint32_t)(((w*16 + arow)*72 + kc*16 + ak8)*2); \
            ldsm4(ah_, aAH_ + aoff_);                                         \
            ldsm4(al_, aAL_ + aoff_);                                         \
            _Pragma("unroll")                                                 \
            for (int nbp = 0; nbp < 4; nbp++) {                               \
                const int n_ = nbp*16 + (mi >> 1)*8 + l8;                     \
                const uint32_t boff_ = (uint32_t)((n_*72 + kc*16 + (mi & 1)*8)*2); \
                ldsm4(bhf_[nbp], aVH_ + boff_);                               \
                ldsm4(blf_[nbp], aVL_ + boff_);                               \
            }                                                                 \
            _Pragma("unroll")                                                 \
            for (int nb = 0; nb < 8; nb++) {                                  \
                const int nbp_ = nb >> 1, sel_ = (nb & 1)*2;                  \
                mma16816(acc[nb], ah_, &bhf_[nbp_][sel_]);                    \
                mma16816(acc[nb], ah_, &blf_[nbp_][sel_]);                    \
                mma16816(acc[nb], al_, &bhf_[nbp_][sel_]);                    \
            }                                                                 \
        } } while (0)

    // prologue
    PV_LOAD(0);
    PV_PROCESS(0, 0);
    __syncthreads();

    for (int c = 0; c < 25; c++) {
        const int bf = c & 1;
        if (c < 24) PV_LOAD(c + 1);
        PV_MMA(bf);
        if (c < 24) PV_PROCESS(c + 1, bf ^ 1);
        __syncthreads();
    }

    // epilogue
    const int r0 = lane >> 2, c0 = (lane & 3)*2;
    const int b = bh >> 3, h = bh & 7;
    const int q1 = q0 + w*16 + r0, q2 = q1 + 8;
    #pragma unroll
    for (int nb = 0; nb < 8; nb++) {
        const int col = h*64 + nb*8 + c0;
        if (q1 < SEQ)
            *(float2*)&out[((size_t)(b*SEQ + q1))*512 + col] = make_float2(acc[nb][0], acc[nb][1]);
        if (q2 < SEQ)
            *(float2*)&out[((size_t)(b*SEQ + q2))*512 + col] = make_float2(acc[nb][2], acc[nb][3]);
    }
}

extern "C" void kernel_launch(void* const* d_in, const int* in_sizes, int n_in,
                              void* d_out, int out_size)
{
    const float* x  = (const float*)d_in[0];
    const float* wq = (const float*)d_in[1];
    const float* bq = (const float*)d_in[2];
    const float* wk = (const float*)d_in[3];
    const float* bk = (const float*)d_in[4];
    const float* wv = (const float*)d_in[5];
    const float* bv = (const float*)d_in[6];
    float* out = (float*)d_out;
    float* p   = out + OUT_ELEMS;

    cudaFuncSetAttribute(score_kernel, cudaFuncAttributeMaxDynamicSharedMemorySize, SC_SMEM_BYTES);
    cudaFuncSetAttribute(pv_kernel,    cudaFuncAttributeMaxDynamicSharedMemorySize, PV_SMEM_BYTES);

    proj_kernel<<<dim3(100, 4, 3), 256>>>(x, wq, bq, wk, bk, wv, bv);
    score_kernel<<<dim3(NKT, 26, BH), 128, SC_SMEM_BYTES>>>(p);
    rowinv_kernel<<<dim3((BH*SEQ + 255)/256), 256>>>();
    pv_kernel<<<dim3(NKT, BH), 256, PV_SMEM_BYTES>>>(p, out);
}

// round 8
// speedup vs baseline: 1.4086x; 1.4086x over previous
#include <cuda_runtime.h>
#include <cuda_bf16.h>
#include <cstdint>

#define SEQ 1600
#define SP  1664
#define BH  64
#define OUT_ELEMS (8*SEQ*512)

// -------------------- scratch --------------------
__device__ __nv_bfloat16 g_qh[(size_t)BH*SP*64];
__device__ __nv_bfloat16 g_ql[(size_t)BH*SP*64];
__device__ __nv_bfloat16 g_kh[(size_t)BH*SP*64];
__device__ __nv_bfloat16 g_kl[(size_t)BH*SP*64];
__device__ __nv_bfloat16 g_vh[(size_t)BH*64*SEQ];   // [bh][d][s]
__device__ __nv_bfloat16 g_vl[(size_t)BH*64*SEQ];
__device__ float g_rowinv[(size_t)BH*SEQ];

// -------------------- f32x2 helpers (proj) --------------------
typedef unsigned long long ull;
__device__ __forceinline__ ull pk2(float a, float b) {
    ull r; asm("mov.b64 %0, {%1, %2};" : "=l"(r) : "f"(a), "f"(b)); return r;
}
__device__ __forceinline__ float2 upk2(ull v) {
    float2 f; asm("mov.b64 {%0, %1}, %2;" : "=f"(f.x), "=f"(f.y) : "l"(v)); return f;
}
__device__ __forceinline__ ull fma2(ull a, ull b, ull c) {
    ull d; asm("fma.rn.f32x2 %0, %1, %2, %3;" : "=l"(d) : "l"(a), "l"(b), "l"(c)); return d;
}

#define MAINSTEP(As_row, Bs_row) do {                                   \
    const float4 a0 = *(const float4*)((As_row) + ty*8);                \
    const float4 a1 = *(const float4*)((As_row) + ty*8 + 4);            \
    const ulonglong2 b0 = *(const ulonglong2*)((Bs_row) + tx*8);        \
    const ulonglong2 b1 = *(const ulonglong2*)((Bs_row) + tx*8 + 4);    \
    const float av[8] = {a0.x,a0.y,a0.z,a0.w,a1.x,a1.y,a1.z,a1.w};      \
    _Pragma("unroll")                                                   \
    for (int _i = 0; _i < 8; _i++) {                                    \
        const ull aa = pk2(av[_i], av[_i]);                             \
        acc[_i][0] = fma2(aa, b0.x, acc[_i][0]);                        \
        acc[_i][1] = fma2(aa, b0.y, acc[_i][1]);                        \
        acc[_i][2] = fma2(aa, b1.x, acc[_i][2]);                        \
        acc[_i][3] = fma2(aa, b1.y, acc[_i][3]);                        \
    } } while (0)

// -------------------- mma.sync / ldmatrix --------------------
__device__ __forceinline__ uint32_t smem_u32(const void* p_) {
    uint32_t a;
    asm("{ .reg .u64 t; cvta.to.shared.u64 t, %1; cvt.u32.u64 %0, t; }" : "=r"(a) : "l"(p_));
    return a;
}
__device__ __forceinline__ void ldsm4(uint32_t* r, uint32_t addr) {
    asm volatile("ldmatrix.sync.aligned.m8n8.x4.shared.b16 {%0,%1,%2,%3}, [%4];"
                 : "=r"(r[0]), "=r"(r[1]), "=r"(r[2]), "=r"(r[3]) : "r"(addr));
}
__device__ __forceinline__ void mma16816(float* d, const uint32_t* a, const uint32_t* b) {
    asm volatile("mma.sync.aligned.m16n8k16.row.col.f32.bf16.bf16.f32 "
                 "{%0,%1,%2,%3}, {%4,%5,%6,%7}, {%8,%9}, {%0,%1,%2,%3};"
                 : "+f"(d[0]), "+f"(d[1]), "+f"(d[2]), "+f"(d[3])
                 : "r"(a[0]), "r"(a[1]), "r"(a[2]), "r"(a[3]), "r"(b[0]), "r"(b[1]));
}

// ==================== K1: QKV projection ====================
__global__ __launch_bounds__(256) void proj_kernel(
    const float* __restrict__ x,
    const float* __restrict__ wq, const float* __restrict__ bq,
    const float* __restrict__ wk, const float* __restrict__ bk,
    const float* __restrict__ wv, const float* __restrict__ bv)
{
    __shared__ __align__(16) float As[16*132];
    __shared__ __align__(16) float Bs[16*132];
    const int tid = threadIdx.x, tx = tid & 15, ty = tid >> 4;
    const int m0 = blockIdx.x*128, n0 = blockIdx.y*128, mat = blockIdx.z;
    const float* w  = (mat==0) ? wq : ((mat==1) ? wk : wv);
    const float* bb = (mat==0) ? bq : ((mat==1) ? bk : bv);

    ull acc[8][4];
    #pragma unroll
    for (int i = 0; i < 8; i++)
        #pragma unroll
        for (int j = 0; j < 4; j++) acc[i][j] = 0ULL;

    for (int kc = 0; kc < 256; kc += 16) {
        #pragma unroll
        for (int j = 0; j < 2; j++) {
            const int idx = tid + j*256;
            const int r = idx >> 2, c4 = idx & 3;
            float4 v = *(const float4*)&x[(size_t)(m0 + r)*256 + kc + c4*4];
            As[(c4*4+0)*132 + r] = v.x;
            As[(c4*4+1)*132 + r] = v.y;
            As[(c4*4+2)*132 + r] = v.z;
            As[(c4*4+3)*132 + r] = v.w;
        }
        #pragma unroll
        for (int j = 0; j < 2; j++) {
            const int idx = tid + j*256;
            const int r = idx >> 5, c = idx & 31;
            *(float4*)&Bs[r*132 + c*4] = *(const float4*)&w[(size_t)(kc + r)*512 + n0 + c*4];
        }
        __syncthreads();
        #pragma unroll
        for (int kk = 0; kk < 16; kk++) MAINSTEP(&As[kk*132], &Bs[kk*132]);
        __syncthreads();
    }

    const int n_base = n0 + tx*8;
    const int h = n_base >> 6, d0 = n_base & 63;
    float b8[8];
    #pragma unroll
    for (int j = 0; j < 8; j++) b8[j] = bb[n_base + j];

    const int m_base = m0 + ty*8;
    const int bI = m_base / SEQ, sI0 = m_base % SEQ;
    const int bh = bI*8 + h;

    if (mat == 2) {
        #pragma unroll
        for (int j = 0; j < 8; j++) {
            uint32_t hp[4], lp[4];
            #pragma unroll
            for (int i2 = 0; i2 < 4; i2++) {
                float v0, v1;
                {
                    float2 t = upk2(acc[i2*2][j>>1]);
                    v0 = ((j & 1) ? t.y : t.x) + b8[j];
                }
                {
                    float2 t = upk2(acc[i2*2+1][j>>1]);
                    v1 = ((j & 1) ? t.y : t.x) + b8[j];
                }
                v0 = fmaxf(v0, 0.f); v1 = fmaxf(v1, 0.f);
                __nv_bfloat16 h0 = __float2bfloat16(v0), h1 = __float2bfloat16(v1);
                __nv_bfloat16 l0 = __float2bfloat16(v0 - __bfloat162float(h0));
                __nv_bfloat16 l1 = __float2bfloat16(v1 - __bfloat162float(h1));
                hp[i2] = (uint32_t)__bfloat16_as_ushort(h0) | ((uint32_t)__bfloat16_as_ushort(h1) << 16);
                lp[i2] = (uint32_t)__bfloat16_as_ushort(l0) | ((uint32_t)__bfloat16_as_ushort(l1) << 16);
            }
            const size_t off = ((size_t)bh*64 + d0 + j)*SEQ + sI0;
            *(uint4*)&g_vh[off] = make_uint4(hp[0], hp[1], hp[2], hp[3]);
            *(uint4*)&g_vl[off] = make_uint4(lp[0], lp[1], lp[2], lp[3]);
        }
    } else {
        const float sc = (mat == 0) ? 0.125f : 1.0f;
        __nv_bfloat16* dh = (mat == 0) ? g_qh : g_kh;
        __nv_bfloat16* dl = (mat == 0) ? g_ql : g_kl;
        #pragma unroll
        for (int i = 0; i < 8; i++) {
            float o[8];
            #pragma unroll
            for (int j = 0; j < 4; j++) {
                float2 t = upk2(acc[i][j]);
                o[j*2] = (t.x + b8[j*2]) * sc; o[j*2+1] = (t.y + b8[j*2+1]) * sc;
            }
            uint32_t hw[4], lw[4];
            #pragma unroll
            for (int j = 0; j < 4; j++) {
                __nv_bfloat16 h0 = __float2bfloat16(o[j*2]);
                __nv_bfloat16 h1 = __float2bfloat16(o[j*2+1]);
                __nv_bfloat16 l0 = __float2bfloat16(o[j*2]   - __bfloat162float(h0));
                __nv_bfloat16 l1 = __float2bfloat16(o[j*2+1] - __bfloat162float(h1));
                hw[j] = (uint32_t)__bfloat16_as_ushort(h0) | ((uint32_t)__bfloat16_as_ushort(h1) << 16);
                lw[j] = (uint32_t)__bfloat16_as_ushort(l0) | ((uint32_t)__bfloat16_as_ushort(l1) << 16);
            }
            const size_t off = ((size_t)bh*SP + sI0 + i)*64 + d0;
            *(uint4*)&dh[off] = make_uint4(hw[0], hw[1], hw[2], hw[3]);
            *(uint4*)&dl[off] = make_uint4(lw[0], lw[1], lw[2], lw[3]);
        }
    }
}

// ==================== K2: fused attention (QK^T -> exp -> e store -> PV) ====================
// smem halves: QH[64*72] QL KH[64*72] KL VH[64*72] VL  = 6*4608 halves = 55296 B
#define FA_TILE 4608
#define FA_SMEM_BYTES (6*FA_TILE*2)

__global__ __launch_bounds__(128) void fused_attn_kernel(float* __restrict__ p,
                                                         float* __restrict__ out)
{
    extern __shared__ __align__(16) __nv_bfloat16 sm[];
    __nv_bfloat16* QH = sm;
    __nv_bfloat16* QL = sm + FA_TILE;
    __nv_bfloat16* KH = sm + 2*FA_TILE;
    __nv_bfloat16* KL = sm + 3*FA_TILE;
    __nv_bfloat16* VH = sm + 4*FA_TILE;
    __nv_bfloat16* VL = sm + 5*FA_TILE;

    const int tid = threadIdx.x, w = tid >> 5, lane = tid & 31;
    const int qt = blockIdx.x, bh = blockIdx.y;
    const int q0 = qt*64;

    // ---- load Q tile once ----
    {
        const uint4* sqh = (const uint4*)(g_qh + ((size_t)bh*SP + q0)*64);
        const uint4* sql = (const uint4*)(g_ql + ((size_t)bh*SP + q0)*64);
        #pragma unroll
        for (int it = 0; it < 4; it++) {
            const int i = tid + it*128;            // 0..511
            const int r = i >> 3, c8 = (i & 7)*8;
            *(uint4*)&QH[r*72 + c8] = sqh[i];
            *(uint4*)&QL[r*72 + c8] = sql[i];
        }
    }

    const uint32_t aQH = smem_u32(QH), aQL = smem_u32(QL);
    const uint32_t aKH = smem_u32(KH), aKL = smem_u32(KL);
    const uint32_t aVH = smem_u32(VH), aVL = smem_u32(VL);

    // fragment addressing
    const int arow = lane & 15, ak8 = (lane >> 4)*8;
    const int mi = lane >> 3, l8 = lane & 7;
    const int brow8 = (mi >> 1)*8 + l8, bk8 = (mi & 1)*8;
    const int r0 = lane >> 2, c0 = (lane & 3)*2;

    const int q1 = q0 + w*16 + r0, q2 = q1 + 8;
    const int qf1 = q1 / 25, qf2 = q2 / 25;
    float* prow1 = p + ((size_t)bh*SEQ + q1)*SEQ;
    float* prow2 = p + ((size_t)bh*SEQ + q2)*SEQ;

    float acc_out[8][4];
    #pragma unroll
    for (int i = 0; i < 8; i++)
        #pragma unroll
        for (int j = 0; j < 4; j++) acc_out[i][j] = 0.f;
    float s1 = 0.f, s2 = 0.f;

    for (int c = 0; c < 25; c++) {
        const int s0 = c*64;
        // ---- load K (rows=s, cols=d) and V (rows=d, cols=s) ----
        #pragma unroll
        for (int it = 0; it < 4; it++) {
            const int i = tid + it*128;
            const int r = i >> 3, c8 = (i & 7)*8;
            const size_t ks = ((size_t)bh*SP + s0 + r)*64 + c8;
            *(uint4*)&KH[r*72 + c8] = *(const uint4*)&g_kh[ks];
            *(uint4*)&KL[r*72 + c8] = *(const uint4*)&g_kl[ks];
            const size_t vs = ((size_t)bh*64 + r)*SEQ + s0 + c8;
            *(uint4*)&VH[r*72 + c8] = *(const uint4*)&g_vh[vs];
            *(uint4*)&VL[r*72 + c8] = *(const uint4*)&g_vl[vs];
        }
        __syncthreads();

        // ---- QK^T : eacc[nb][4], nb = s-block (n dim) ----
        float eacc[8][4];
        #pragma unroll
        for (int i = 0; i < 8; i++)
            #pragma unroll
            for (int j = 0; j < 4; j++) eacc[i][j] = 0.f;

        #pragma unroll
        for (int kc = 0; kc < 4; kc++) {
            uint32_t ah[4], al[4], bkh[4][4], bkl[4][4];
            const uint32_t aoff = (uint32_t)(((w*16 + arow)*72 + kc*16 + ak8)*2);
            ldsm4(ah, aQH + aoff);
            ldsm4(al, aQL + aoff);
            #pragma unroll
            for (int nbp = 0; nbp < 4; nbp++) {
                const uint32_t boff = (uint32_t)(((nbp*16 + brow8)*72 + kc*16 + bk8)*2);
                ldsm4(bkh[nbp], aKH + boff);
                ldsm4(bkl[nbp], aKL + boff);
            }
            #pragma unroll
            for (int nb = 0; nb < 8; nb++) {
                const int nbp = nb >> 1, sel = (nb & 1)*2;
                mma16816(eacc[nb], ah, &bkh[nbp][sel]);
                mma16816(eacc[nb], ah, &bkl[nbp][sel]);
                mma16816(eacc[nb], al, &bkh[nbp][sel]);
            }
        }

        // ---- mask + exp + store raw e + rowsum ----
        #pragma unroll
        for (int nb = 0; nb < 8; nb++) {
            const int k = s0 + nb*8 + c0;
            const int kfa = k / 25, kfb = (k + 1) / 25;
            float e0 = (qf1 != kfa || q1 == k  ) ? __expf(eacc[nb][0]) : 0.f;
            float e1 = (qf1 != kfb || q1 == k+1) ? __expf(eacc[nb][1]) : 0.f;
            float e2 = (qf2 != kfa || q2 == k  ) ? __expf(eacc[nb][2]) : 0.f;
            float e3 = (qf2 != kfb || q2 == k+1) ? __expf(eacc[nb][3]) : 0.f;
            s1 += e0 + e1; s2 += e2 + e3;
            *(float2*)&prow1[k] = make_float2(e0, e1);
            *(float2*)&prow2[k] = make_float2(e2, e3);
            eacc[nb][0] = e0; eacc[nb][1] = e1; eacc[nb][2] = e2; eacc[nb][3] = e3;
        }

        // ---- PV: A = e (in-register frags), B = V ----
        #pragma unroll
        for (int kc2 = 0; kc2 < 4; kc2++) {
            uint32_t ahx[4], alx[4];
            #pragma unroll
            for (int half = 0; half < 2; half++) {
                const float* e4 = eacc[kc2*2 + half];
                __nv_bfloat162 h01 = __float22bfloat162_rn(make_float2(e4[0], e4[1]));
                __nv_bfloat162 h23 = __float22bfloat162_rn(make_float2(e4[2], e4[3]));
                float2 hf01 = __bfloat1622float2(h01), hf23 = __bfloat1622float2(h23);
                __nv_bfloat162 l01 = __float22bfloat162_rn(make_float2(e4[0]-hf01.x, e4[1]-hf01.y));
                __nv_bfloat162 l23 = __float22bfloat162_rn(make_float2(e4[2]-hf23.x, e4[3]-hf23.y));
                ahx[half*2+0] = *(uint32_t*)&h01;   // (r,   k pair)
                ahx[half*2+1] = *(uint32_t*)&h23;   // (r+8, k pair)
                alx[half*2+0] = *(uint32_t*)&l01;
                alx[half*2+1] = *(uint32_t*)&l23;
            }
            // A frag order: a0=(r,k0k1) a1=(r+8,k0k1) a2=(r,k8k9) a3=(r+8,k8k9)
            // half0 (cols 0-7) -> a0,a1 ; half1 (cols 8-15) -> a2,a3  (already in order)
            uint32_t bvh[4][4], bvl[4][4];
            #pragma unroll
            for (int nbp = 0; nbp < 4; nbp++) {
                const uint32_t boff = (uint32_t)(((nbp*16 + brow8)*72 + kc2*16 + bk8)*2);
                ldsm4(bvh[nbp], aVH + boff);
                ldsm4(bvl[nbp], aVL + boff);
            }
            #pragma unroll
            for (int nb = 0; nb < 8; nb++) {
                const int nbp = nb >> 1, sel = (nb & 1)*2;
                mma16816(acc_out[nb], ahx, &bvh[nbp][sel]);
                mma16816(acc_out[nb], ahx, &bvl[nbp][sel]);
                mma16816(acc_out[nb], alx, &bvh[nbp][sel]);
            }
        }
        __syncthreads();
    }

    // ---- epilogue: rowsum reduce, rowinv, scale, store out ----
    s1 += __shfl_xor_sync(0xffffffffu, s1, 1);
    s1 += __shfl_xor_sync(0xffffffffu, s1, 2);
    s2 += __shfl_xor_sync(0xffffffffu, s2, 1);
    s2 += __shfl_xor_sync(0xffffffffu, s2, 2);
    const float rv1 = 1.0f / s1, rv2 = 1.0f / s2;
    if ((lane & 3) == 0) {
        g_rowinv[(size_t)bh*SEQ + q1] = rv1;
        g_rowinv[(size_t)bh*SEQ + q2] = rv2;
    }
    const int b = bh >> 3, h = bh & 7;
    #pragma unroll
    for (int nb = 0; nb < 8; nb++) {
        const int col = h*64 + nb*8 + c0;
        *(float2*)&out[((size_t)(b*SEQ + q1))*512 + col] =
            make_float2(acc_out[nb][0]*rv1, acc_out[nb][1]*rv1);
        *(float2*)&out[((size_t)(b*SEQ + q2))*512 + col] =
            make_float2(acc_out[nb][2]*rv2, acc_out[nb][3]*rv2);
    }
}

// ==================== K3: normalize p (streaming) ====================
__global__ __launch_bounds__(256) void norm_kernel(float* __restrict__ p)
{
    const size_t i4 = (size_t)blockIdx.x*256 + threadIdx.x;   // float4 index
    const int row = (int)(i4 / 400);                          // 1600/4 per row
    const float rv = g_rowinv[row];
    float4 v = ((const float4*)p)[i4];
    v.x *= rv; v.y *= rv; v.z *= rv; v.w *= rv;
    ((float4*)p)[i4] = v;
}

extern "C" void kernel_launch(void* const* d_in, const int* in_sizes, int n_in,
                              void* d_out, int out_size)
{
    const float* x  = (const float*)d_in[0];
    const float* wq = (const float*)d_in[1];
    const float* bq = (const float*)d_in[2];
    const float* wk = (const float*)d_in[3];
    const float* bk = (const float*)d_in[4];
    const float* wv = (const float*)d_in[5];
    const float* bv = (const float*)d_in[6];
    float* out = (float*)d_out;
    float* p   = out + OUT_ELEMS;

    cudaFuncSetAttribute(fused_attn_kernel, cudaFuncAttributeMaxDynamicSharedMemorySize, FA_SMEM_BYTES);

    proj_kernel<<<dim3(100, 4, 3), 256>>>(x, wq, bq, wk, bk, wv, bv);
    fused_attn_kernel<<<dim3(25, BH), 128, FA_SMEM_BYTES>>>(p, out);
    norm_kernel<<<dim3((int)(((size_t)BH*SEQ*400 + 255)/256)), 256>>>(p);
}

// round 9
// speedup vs baseline: 1.7246x; 1.2243x over previous
#include <cuda_runtime.h>
#include <cuda_bf16.h>
#include <cstdint>

#define SEQ 1600
#define BH  64
#define OUT_ELEMS (8*SEQ*512)

// -------------------- scratch --------------------
__device__ __nv_bfloat16 g_qh[(size_t)BH*SEQ*64];
__device__ __nv_bfloat16 g_ql[(size_t)BH*SEQ*64];
__device__ __nv_bfloat16 g_kh[(size_t)BH*SEQ*64];
__device__ __nv_bfloat16 g_kl[(size_t)BH*SEQ*64];
__device__ __nv_bfloat16 g_vh[(size_t)BH*SEQ*64];   // [bh][s][d] natural
__device__ __nv_bfloat16 g_vl[(size_t)BH*SEQ*64];
__device__ __nv_bfloat16 g_wth[3*512*256];          // [mat][n][k] transposed
__device__ __nv_bfloat16 g_wtl[3*512*256];
__device__ float g_rowinv[(size_t)BH*SEQ];

// -------------------- mma.sync / ldmatrix --------------------
__device__ __forceinline__ uint32_t smem_u32(const void* p_) {
    uint32_t a;
    asm("{ .reg .u64 t; cvta.to.shared.u64 t, %1; cvt.u32.u64 %0, t; }" : "=r"(a) : "l"(p_));
    return a;
}
__device__ __forceinline__ void ldsm4(uint32_t* r, uint32_t addr) {
    asm volatile("ldmatrix.sync.aligned.m8n8.x4.shared.b16 {%0,%1,%2,%3}, [%4];"
                 : "=r"(r[0]), "=r"(r[1]), "=r"(r[2]), "=r"(r[3]) : "r"(addr));
}
__device__ __forceinline__ void ldsm4t(uint32_t* r, uint32_t addr) {
    asm volatile("ldmatrix.sync.aligned.m8n8.x4.trans.shared.b16 {%0,%1,%2,%3}, [%4];"
                 : "=r"(r[0]), "=r"(r[1]), "=r"(r[2]), "=r"(r[3]) : "r"(addr));
}
__device__ __forceinline__ void mma16816(float* d, const uint32_t* a, const uint32_t* b) {
    asm volatile("mma.sync.aligned.m16n8k16.row.col.f32.bf16.bf16.f32 "
                 "{%0,%1,%2,%3}, {%4,%5,%6,%7}, {%8,%9}, {%0,%1,%2,%3};"
                 : "+f"(d[0]), "+f"(d[1]), "+f"(d[2]), "+f"(d[3])
                 : "r"(a[0]), "r"(a[1]), "r"(a[2]), "r"(a[3]), "r"(b[0]), "r"(b[1]));
}
__device__ __forceinline__ void split2(float a, float b, uint32_t& hi, uint32_t& lo) {
    __nv_bfloat162 h = __float22bfloat162_rn(make_float2(a, b));
    float2 hf = __bfloat1622float2(h);
    __nv_bfloat162 l = __float22bfloat162_rn(make_float2(a - hf.x, b - hf.y));
    hi = *(uint32_t*)&h; lo = *(uint32_t*)&l;
}

// ==================== K0: transpose + split W ====================
__global__ __launch_bounds__(256) void convert_w_kernel(
    const float* __restrict__ wq, const float* __restrict__ wk, const float* __restrict__ wv)
{
    const int idx = blockIdx.x*256 + threadIdx.x;      // 0 .. 393215
    const int mat = idx >> 17;
    const int rem = idx & 131071;
    const int k = rem >> 9, n = rem & 511;
    const float* w = (mat == 0) ? wq : ((mat == 1) ? wk : wv);
    const float v = w[rem];
    __nv_bfloat16 h = __float2bfloat16(v);
    __nv_bfloat16 l = __float2bfloat16(v - __bfloat162float(h));
    const size_t off = ((size_t)mat << 17) + (size_t)n*256 + k;
    g_wth[off] = h; g_wtl[off] = l;
}

// ==================== K1: QKV projection via mma ====================
// smem halves: XH[128*72] XL WH[128*72] WL = 73728 B
#define PJ_TILE 9216
#define PJ_SMEM_BYTES (4*PJ_TILE*2)

__global__ __launch_bounds__(256, 2) void proj_kernel(
    const float* __restrict__ x,
    const float* __restrict__ bq, const float* __restrict__ bk, const float* __restrict__ bv)
{
    extern __shared__ __align__(16) __nv_bfloat16 sm[];
    __nv_bfloat16* XH = sm;
    __nv_bfloat16* XL = sm + PJ_TILE;
    __nv_bfloat16* WH = sm + 2*PJ_TILE;
    __nv_bfloat16* WL = sm + 3*PJ_TILE;

    const int tid = threadIdx.x, w = tid >> 5, lane = tid & 31;
    const int m0 = blockIdx.x*128, n0 = blockIdx.y*128, mat = blockIdx.z;
    const float* bb = (mat == 0) ? bq : ((mat == 1) ? bk : bv);
    const __nv_bfloat16* wth = g_wth + ((size_t)mat << 17);
    const __nv_bfloat16* wtl = g_wtl + ((size_t)mat << 17);

    float acc[16][4];
    #pragma unroll
    for (int i = 0; i < 16; i++)
        #pragma unroll
        for (int j = 0; j < 4; j++) acc[i][j] = 0.f;

    const uint32_t aXH = smem_u32(XH), aXL = smem_u32(XL);
    const uint32_t aWH = smem_u32(WH), aWL = smem_u32(WL);

    const int arow = lane & 15, ak8 = (lane >> 4)*8;
    const int mi = lane >> 3, l8 = lane & 7;
    const int brow8 = (mi >> 1)*8 + l8, bk8 = (mi & 1)*8;

    for (int kc = 0; kc < 256; kc += 64) {
        // X fp32 -> bf16 hi/lo into smem
        #pragma unroll
        for (int j = 0; j < 8; j++) {
            const int idx = tid + j*256;           // 0..2047
            const int r = idx >> 4, c4 = idx & 15;
            const float4 v = *(const float4*)&x[(size_t)(m0 + r)*256 + kc + c4*4];
            uint32_t h01, l01, h23, l23;
            split2(v.x, v.y, h01, l01);
            split2(v.z, v.w, h23, l23);
            *(uint2*)&XH[r*72 + c4*4] = make_uint2(h01, h23);
            *(uint2*)&XL[r*72 + c4*4] = make_uint2(l01, l23);
        }
        // W^T bf16 tiles
        #pragma unroll
        for (int j = 0; j < 4; j++) {
            const int idx = tid + j*256;           // 0..1023
            const int r = idx >> 3, c8 = (idx & 7)*8;
            const size_t off = (size_t)(n0 + r)*256 + kc + c8;
            *(uint4*)&WH[r*72 + c8] = *(const uint4*)&wth[off];
            *(uint4*)&WL[r*72 + c8] = *(const uint4*)&wtl[off];
        }
        __syncthreads();

        #pragma unroll
        for (int kc16 = 0; kc16 < 4; kc16++) {
            uint32_t ah[4], al[4];
            const uint32_t aoff = (uint32_t)(((w*16 + arow)*72 + kc16*16 + ak8)*2);
            ldsm4(ah, aXH + aoff);
            ldsm4(al, aXL + aoff);
            #pragma unroll
            for (int nbp = 0; nbp < 8; nbp++) {
                uint32_t bhf[4], blf[4];
                const uint32_t boff = (uint32_t)(((nbp*16 + brow8)*72 + kc16*16 + bk8)*2);
                ldsm4(bhf, aWH + boff);
                ldsm4(blf, aWL + boff);
                #pragma unroll
                for (int half = 0; half < 2; half++) {
                    const int nb = nbp*2 + half, sel = half*2;
                    mma16816(acc[nb], ah, &bhf[sel]);
                    mma16816(acc[nb], ah, &blf[sel]);
                    mma16816(acc[nb], al, &bhf[sel]);
                }
            }
        }
        __syncthreads();
    }

    // epilogue
    const int r0 = lane >> 2, c0 = (lane & 3)*2;
    const int m1 = m0 + w*16 + r0, m2 = m1 + 8;
    const int bI1 = m1 / SEQ, s1 = m1 % SEQ;
    const int bI2 = m2 / SEQ, s2 = m2 % SEQ;
    const float sc = (mat == 0) ? 0.125f : 1.0f;
    __nv_bfloat16* dh = (mat == 0) ? g_qh : ((mat == 1) ? g_kh : g_vh);
    __nv_bfloat16* dl = (mat == 0) ? g_ql : ((mat == 1) ? g_kl : g_vl);

    #pragma unroll
    for (int nb = 0; nb < 16; nb++) {
        const int n = n0 + nb*8 + c0;
        const int h = n >> 6, d = n & 63;
        const float b0 = bb[n], b1 = bb[n + 1];
        #pragma unroll
        for (int rr = 0; rr < 2; rr++) {
            float v0 = acc[nb][rr*2]     + b0;
            float v1 = acc[nb][rr*2 + 1] + b1;
            v0 *= sc; v1 *= sc;
            if (mat == 2) { v0 = fmaxf(v0, 0.f); v1 = fmaxf(v1, 0.f); }
            uint32_t hi, lo;
            split2(v0, v1, hi, lo);
            const int bI = rr ? bI2 : bI1;
            const int s  = rr ? s2  : s1;
            const size_t off = ((size_t)(bI*8 + h)*SEQ + s)*64 + d;
            *(uint32_t*)&dh[off] = hi;
            *(uint32_t*)&dl[off] = lo;
        }
    }
}

// ==================== K2: fused attention ====================
// smem halves: QH[64*72] QL KH KL VH VL = 55296 B
#define FA_TILE 4608
#define FA_SMEM_BYTES (6*FA_TILE*2)

__global__ __launch_bounds__(128) void fused_attn_kernel(float* __restrict__ p,
                                                         float* __restrict__ out)
{
    extern __shared__ __align__(16) __nv_bfloat16 sm[];
    __nv_bfloat16* QH = sm;
    __nv_bfloat16* QL = sm + FA_TILE;
    __nv_bfloat16* KH = sm + 2*FA_TILE;
    __nv_bfloat16* KL = sm + 3*FA_TILE;
    __nv_bfloat16* VH = sm + 4*FA_TILE;
    __nv_bfloat16* VL = sm + 5*FA_TILE;

    const int tid = threadIdx.x, w = tid >> 5, lane = tid & 31;
    const int qt = blockIdx.x, bh = blockIdx.y;
    const int q0 = qt*64;

    // ---- load Q tile once ----
    {
        const uint4* sqh = (const uint4*)(g_qh + ((size_t)bh*SEQ + q0)*64);
        const uint4* sql = (const uint4*)(g_ql + ((size_t)bh*SEQ + q0)*64);
        #pragma unroll
        for (int it = 0; it < 4; it++) {
            const int i = tid + it*128;
            const int r = i >> 3, c8 = (i & 7)*8;
            *(uint4*)&QH[r*72 + c8] = sqh[i];
            *(uint4*)&QL[r*72 + c8] = sql[i];
        }
    }

    const uint32_t aQH = smem_u32(QH), aQL = smem_u32(QL);
    const uint32_t aKH = smem_u32(KH), aKL = smem_u32(KL);
    const uint32_t aVH = smem_u32(VH), aVL = smem_u32(VL);

    const int arow = lane & 15, ak8 = (lane >> 4)*8;
    const int mi = lane >> 3, l8 = lane & 7;
    const int brow8 = (mi >> 1)*8 + l8, bk8 = (mi & 1)*8;
    // trans (V) addressing: row = k (s), col = n (d)
    const int tk8 = (mi & 1)*8, tn8 = (mi >> 1)*8;
    const int r0 = lane >> 2, c0 = (lane & 3)*2;

    const int q1 = q0 + w*16 + r0, q2 = q1 + 8;
    const int qf1 = q1 / 25, qf2 = q2 / 25;
    float* prow1 = p + ((size_t)bh*SEQ + q1)*SEQ;
    float* prow2 = p + ((size_t)bh*SEQ + q2)*SEQ;

    float acc_out[8][4];
    #pragma unroll
    for (int i = 0; i < 8; i++)
        #pragma unroll
        for (int j = 0; j < 4; j++) acc_out[i][j] = 0.f;
    float s1 = 0.f, s2 = 0.f;

    for (int c = 0; c < 25; c++) {
        const int s0 = c*64;
        // ---- load K and V tiles (both [s][d] natural) ----
        #pragma unroll
        for (int it = 0; it < 4; it++) {
            const int i = tid + it*128;
            const int r = i >> 3, c8 = (i & 7)*8;
            const size_t gs = ((size_t)bh*SEQ + s0 + r)*64 + c8;
            *(uint4*)&KH[r*72 + c8] = *(const uint4*)&g_kh[gs];
            *(uint4*)&KL[r*72 + c8] = *(const uint4*)&g_kl[gs];
            *(uint4*)&VH[r*72 + c8] = *(const uint4*)&g_vh[gs];
            *(uint4*)&VL[r*72 + c8] = *(const uint4*)&g_vl[gs];
        }
        __syncthreads();

        // ---- QK^T ----
        float eacc[8][4];
        #pragma unroll
        for (int i = 0; i < 8; i++)
            #pragma unroll
            for (int j = 0; j < 4; j++) eacc[i][j] = 0.f;

        #pragma unroll
        for (int kc = 0; kc < 4; kc++) {
            uint32_t ah[4], al[4], bkh[4][4], bkl[4][4];
            const uint32_t aoff = (uint32_t)(((w*16 + arow)*72 + kc*16 + ak8)*2);
            ldsm4(ah, aQH + aoff);
            ldsm4(al, aQL + aoff);
            #pragma unroll
            for (int nbp = 0; nbp < 4; nbp++) {
                const uint32_t boff = (uint32_t)(((nbp*16 + brow8)*72 + kc*16 + bk8)*2);
                ldsm4(bkh[nbp], aKH + boff);
                ldsm4(bkl[nbp], aKL + boff);
            }
            #pragma unroll
            for (int nb = 0; nb < 8; nb++) {
                const int nbp = nb >> 1, sel = (nb & 1)*2;
                mma16816(eacc[nb], ah, &bkh[nbp][sel]);
                mma16816(eacc[nb], ah, &bkl[nbp][sel]);
                mma16816(eacc[nb], al, &bkh[nbp][sel]);
            }
        }

        // ---- mask + exp + store raw e + rowsum ----
        #pragma unroll
        for (int nb = 0; nb < 8; nb++) {
            const int k = s0 + nb*8 + c0;
            const int kfa = k / 25, kfb = (k + 1) / 25;
            float e0 = (qf1 != kfa || q1 == k  ) ? __expf(eacc[nb][0]) : 0.f;
            float e1 = (qf1 != kfb || q1 == k+1) ? __expf(eacc[nb][1]) : 0.f;
            float e2 = (qf2 != kfa || q2 == k  ) ? __expf(eacc[nb][2]) : 0.f;
            float e3 = (qf2 != kfb || q2 == k+1) ? __expf(eacc[nb][3]) : 0.f;
            s1 += e0 + e1; s2 += e2 + e3;
            *(float2*)&prow1[k] = make_float2(e0, e1);
            *(float2*)&prow2[k] = make_float2(e2, e3);
            eacc[nb][0] = e0; eacc[nb][1] = e1; eacc[nb][2] = e2; eacc[nb][3] = e3;
        }

        // ---- PV: A = e (in-register frags), B = V via ldmatrix.trans ----
        #pragma unroll
        for (int kc2 = 0; kc2 < 4; kc2++) {
            uint32_t ahx[4], alx[4];
            #pragma unroll
            for (int half = 0; half < 2; half++) {
                const float* e4 = eacc[kc2*2 + half];
                uint32_t h01, l01, h23, l23;
                split2(e4[0], e4[1], h01, l01);
                split2(e4[2], e4[3], h23, l23);
                ahx[half*2+0] = h01; ahx[half*2+1] = h23;
                alx[half*2+0] = l01; alx[half*2+1] = l23;
            }
            uint32_t bvh[4][4], bvl[4][4];
            #pragma unroll
            for (int nbp = 0; nbp < 4; nbp++) {
                const uint32_t boff = (uint32_t)(((kc2*16 + tk8 + l8)*72 + nbp*16 + tn8)*2);
                ldsm4t(bvh[nbp], aVH + boff);
                ldsm4t(bvl[nbp], aVL + boff);
            }
            #pragma unroll
            for (int nb = 0; nb < 8; nb++) {
                const int nbp = nb >> 1, sel = (nb & 1)*2;
                mma16816(acc_out[nb], ahx, &bvh[nbp][sel]);
                mma16816(acc_out[nb], ahx, &bvl[nbp][sel]);
                mma16816(acc_out[nb], alx, &bvh[nbp][sel]);
            }
        }
        __syncthreads();
    }

    // ---- epilogue ----
    s1 += __shfl_xor_sync(0xffffffffu, s1, 1);
    s1 += __shfl_xor_sync(0xffffffffu, s1, 2);
    s2 += __shfl_xor_sync(0xffffffffu, s2, 1);
    s2 += __shfl_xor_sync(0xffffffffu, s2, 2);
    const float rv1 = 1.0f / s1, rv2 = 1.0f / s2;
    if ((lane & 3) == 0) {
        g_rowinv[(size_t)bh*SEQ + q1] = rv1;
        g_rowinv[(size_t)bh*SEQ + q2] = rv2;
    }
    const int b = bh >> 3, h = bh & 7;
    #pragma unroll
    for (int nb = 0; nb < 8; nb++) {
        const int col = h*64 + nb*8 + c0;
        *(float2*)&out[((size_t)(b*SEQ + q1))*512 + col] =
            make_float2(acc_out[nb][0]*rv1, acc_out[nb][1]*rv1);
        *(float2*)&out[((size_t)(b*SEQ + q2))*512 + col] =
            make_float2(acc_out[nb][2]*rv2, acc_out[nb][3]*rv2);
    }
}

// ==================== K3: normalize p (streaming) ====================
__global__ __launch_bounds__(256) void norm_kernel(float* __restrict__ p)
{
    const size_t i4 = (size_t)blockIdx.x*256 + threadIdx.x;
    const int row = (int)(i4 / 400);
    const float rv = g_rowinv[row];
    float4 v = ((const float4*)p)[i4];
    v.x *= rv; v.y *= rv; v.z *= rv; v.w *= rv;
    ((float4*)p)[i4] = v;
}

extern "C" void kernel_launch(void* const* d_in, const int* in_sizes, int n_in,
                              void* d_out, int out_size)
{
    const float* x  = (const float*)d_in[0];
    const float* wq = (const float*)d_in[1];
    const float* bq = (const float*)d_in[2];
    const float* wk = (const float*)d_in[3];
    const float* bk = (const float*)d_in[4];
    const float* wv = (const float*)d_in[5];
    const float* bv = (const float*)d_in[6];
    float* out = (float*)d_out;
    float* p   = out + OUT_ELEMS;

    cudaFuncSetAttribute(proj_kernel,       cudaFuncAttributeMaxDynamicSharedMemorySize, PJ_SMEM_BYTES);
    cudaFuncSetAttribute(fused_attn_kernel, cudaFuncAttributeMaxDynamicSharedMemorySize, FA_SMEM_BYTES);

    convert_w_kernel<<<1536, 256>>>(wq, wk, wv);
    proj_kernel<<<dim3(100, 4, 3), 256, PJ_SMEM_BYTES>>>(x, bq, bk, bv);
    fused_attn_kernel<<<dim3(25, BH), 128, FA_SMEM_BYTES>>>(p, out);
    norm_kernel<<<dim3((int)(((size_t)BH*SEQ*400 + 255)/256)), 256>>>(p);
}